// round 1
// baseline (speedup 1.0000x reference)
#include <cuda_runtime.h>
#include <math.h>

// Problem constants
#define AMP  257
#define ATT  257
#define NBATCH 8
#define SEQ  2048
#define BT   (NBATCH * SEQ)   // 16384 tokens
#define LDP  264              // padded leading dim for 257 (float4-aligned)

// ---------------------------------------------------------------------------
// Static device scratch (no allocations allowed in kernel_launch)
// ---------------------------------------------------------------------------
__device__ float g_qp[(size_t)BT * LDP];     // projected Q  [BT, 257] ld 264
__device__ float g_kp[(size_t)BT * LDP];     // projected K
__device__ float g_vp[(size_t)BT * LDP];     // projected V
__device__ float g_ctx[(size_t)BT * LDP];    // attention context
__device__ float g_scores[(size_t)NBATCH * SEQ * SEQ]; // sigmoid scores, 134 MB

// ---------------------------------------------------------------------------
// Generic batched SGEMM:
//   C[z][m,n] = epilogue( sum_k A[z][m,k] * B[z][n or k, ...] )
// BKM = true : B is [N,K] row-major, k contiguous  (NT gemm, e.g. x @ W^T)
// BKM = false: B is [K,N] row-major, n contiguous  (NN gemm, e.g. S @ V)
// SIG = true : C = sigmoid(acc * scale)      (no bias)
// SIG = false: C = acc + bias[n]             (bias may be null)
// Tile: 64x64x16, 256 threads, 4x4 per-thread microtile.
// ---------------------------------------------------------------------------
template <bool BKM, bool SIG>
__global__ __launch_bounds__(256)
void gemm_k(const float* __restrict__ A, int lda, long long sA,
            const float* __restrict__ B, int ldb, long long sB,
            float* __restrict__ C, int ldc, long long sC,
            int M, int N, int K,
            const float* __restrict__ bias, float scale)
{
    __shared__ float As[16][64];   // As[k][m]
    __shared__ float Bs[16][64];   // Bs[k][n]

    const int bz = blockIdx.z;
    const float* Ab = A + (long long)bz * sA;
    const float* Bb = B + (long long)bz * sB;
    float*       Cb = C + (long long)bz * sC;

    const int m0 = blockIdx.y * 64;
    const int n0 = blockIdx.x * 64;
    const int tid = threadIdx.x;
    const int tx = tid & 15;        // 0..15 -> 4 output cols
    const int ty = tid >> 4;        // 0..15 -> 4 output rows

    // A-tile loader mapping: 64 rows x 16 k, each thread loads 4 consecutive k
    const int ar = tid >> 2;        // 0..63 row within tile
    const int ak = (tid & 3) * 4;   // 0,4,8,12 k-offset

    float acc[4][4] = {};

    for (int k0 = 0; k0 < K; k0 += 16) {
        // ---- load A tile (transposed into As[k][m]) ----
        {
            const int m = m0 + ar;
            const bool mok = (m < M);
            const float* ap = Ab + (long long)m * lda + k0 + ak;
            #pragma unroll
            for (int i = 0; i < 4; i++) {
                const int k = k0 + ak + i;
                As[ak + i][ar] = (mok && k < K) ? ap[i] : 0.f;
            }
        }
        // ---- load B tile into Bs[k][n] ----
        if (BKM) {
            const int n = n0 + ar;
            const bool nok = (n < N);
            const float* bp = Bb + (long long)n * ldb + k0 + ak;
            #pragma unroll
            for (int i = 0; i < 4; i++) {
                const int k = k0 + ak + i;
                Bs[ak + i][ar] = (nok && k < K) ? bp[i] : 0.f;
            }
        } else {
            const int kr = tid >> 4;          // 0..15
            const int nc = (tid & 15) * 4;    // 0..60
            const int k = k0 + kr;
            const bool kok = (k < K);
            const float* bp = Bb + (long long)k * ldb + n0 + nc;
            #pragma unroll
            for (int i = 0; i < 4; i++) {
                const int n = n0 + nc + i;
                Bs[kr][nc + i] = (kok && n < N) ? bp[i] : 0.f;
            }
        }
        __syncthreads();

        // ---- compute ----
        #pragma unroll
        for (int k = 0; k < 16; k++) {
            float a[4], b[4];
            *(float4*)a = *(const float4*)&As[k][ty * 4];
            *(float4*)b = *(const float4*)&Bs[k][tx * 4];
            #pragma unroll
            for (int i = 0; i < 4; i++)
                #pragma unroll
                for (int j = 0; j < 4; j++)
                    acc[i][j] = fmaf(a[i], b[j], acc[i][j]);
        }
        __syncthreads();
    }

    // ---- epilogue ----
    #pragma unroll
    for (int i = 0; i < 4; i++) {
        const int m = m0 + ty * 4 + i;
        if (m >= M) continue;
        #pragma unroll
        for (int j = 0; j < 4; j++) {
            const int n = n0 + tx * 4 + j;
            if (n >= N) continue;
            float v = acc[i][j];
            if (SIG) {
                v = 1.0f / (1.0f + __expf(-v * scale));
            } else if (bias) {
                v += bias[n];
            }
            Cb[(long long)m * ldc + n] = v;
        }
    }
}

// ---------------------------------------------------------------------------
// Host launch
// ---------------------------------------------------------------------------
static inline int ceil_div(int a, int b) { return (a + b - 1) / b; }

extern "C" void kernel_launch(void* const* d_in, const int* in_sizes, int n_in,
                              void* d_out, int out_size)
{
    const float* q  = (const float*)d_in[0];
    const float* k  = (const float*)d_in[1];
    const float* v  = (const float*)d_in[2];
    const float* Wq = (const float*)d_in[3];
    const float* bq = (const float*)d_in[4];
    const float* Wk = (const float*)d_in[5];
    const float* bk = (const float*)d_in[6];
    const float* Wv = (const float*)d_in[7];
    const float* bv = (const float*)d_in[8];
    const float* Wo = (const float*)d_in[9];
    const float* bo = (const float*)d_in[10];
    float* out = (float*)d_out;

    float *qp, *kp, *vp, *ctx, *scores;
    cudaGetSymbolAddress((void**)&qp,     g_qp);
    cudaGetSymbolAddress((void**)&kp,     g_kp);
    cudaGetSymbolAddress((void**)&vp,     g_vp);
    cudaGetSymbolAddress((void**)&ctx,    g_ctx);
    cudaGetSymbolAddress((void**)&scores, g_scores);

    const float scale = 1.0f / sqrtf((float)AMP);
    const dim3 blk(256);

    // 1) QKV projections: [16384,257] = x[16384,257] @ W[257,257]^T + b
    {
        dim3 grid(ceil_div(ATT, 64), ceil_div(BT, 64), 1);
        gemm_k<true, false><<<grid, blk>>>(q, AMP, 0, Wq, AMP, 0,
                                           qp, LDP, 0, BT, ATT, AMP, bq, 0.f);
        gemm_k<true, false><<<grid, blk>>>(k, AMP, 0, Wk, AMP, 0,
                                           kp, LDP, 0, BT, ATT, AMP, bk, 0.f);
        gemm_k<true, false><<<grid, blk>>>(v, AMP, 0, Wv, AMP, 0,
                                           vp, LDP, 0, BT, ATT, AMP, bv, 0.f);
    }

    // 2) scores[b] = sigmoid( (qp[b] @ kp[b]^T) * scale )   [2048, 2048] x 8
    {
        dim3 grid(ceil_div(SEQ, 64), ceil_div(SEQ, 64), NBATCH);
        gemm_k<true, true><<<grid, blk>>>(
            qp, LDP, (long long)SEQ * LDP,
            kp, LDP, (long long)SEQ * LDP,
            scores, SEQ, (long long)SEQ * SEQ,
            SEQ, SEQ, ATT, nullptr, scale);
    }

    // 3) ctx[b] = scores[b] @ vp[b]   [2048, 257] x 8   (B is [K,N], n-contig)
    {
        dim3 grid(ceil_div(ATT, 64), ceil_div(SEQ, 64), NBATCH);
        gemm_k<false, false><<<grid, blk>>>(
            scores, SEQ, (long long)SEQ * SEQ,
            vp, LDP, (long long)SEQ * LDP,
            ctx, LDP, (long long)SEQ * LDP,
            SEQ, ATT, SEQ, nullptr, 0.f);
    }

    // 4) out = ctx @ Wo^T + bo   [16384, 257]  (batches contiguous in ctx)
    {
        dim3 grid(ceil_div(AMP, 64), ceil_div(BT, 64), 1);
        gemm_k<true, false><<<grid, blk>>>(ctx, LDP, 0, Wo, ATT, 0,
                                           out, AMP, 0, BT, AMP, ATT, bo, 0.f);
    }
}

// round 2
// speedup vs baseline: 1.0018x; 1.0018x over previous
#include <cuda_runtime.h>
#include <math.h>

// Problem constants
#define AMP  257
#define ATT  257
#define NBATCH 8
#define SEQ  2048
#define BT   (NBATCH * SEQ)   // 16384 tokens
#define LDP  264              // padded leading dim for 257 (float4-aligned)

// ---------------------------------------------------------------------------
// Static device scratch (no allocations allowed in kernel_launch)
// ---------------------------------------------------------------------------
__device__ float g_qp[(size_t)BT * LDP];     // projected Q  [BT, 257] ld 264
__device__ float g_kp[(size_t)BT * LDP];     // projected K
__device__ float g_vp[(size_t)BT * LDP];     // projected V
__device__ float g_ctx[(size_t)BT * LDP];    // attention context
__device__ float g_scores[(size_t)NBATCH * SEQ * SEQ]; // sigmoid scores, 134 MB

// ---------------------------------------------------------------------------
// Generic batched SGEMM:
//   C[z][m,n] = epilogue( sum_k A[z][m,k] * B[z][n or k, ...] )
// BKM = true : B is [N,K] row-major, k contiguous  (NT gemm, e.g. x @ W^T)
// BKM = false: B is [K,N] row-major, n contiguous  (NN gemm, e.g. S @ V)
// SIG = true : C = sigmoid(acc * scale)      (no bias)
// SIG = false: C = acc + bias[n]             (bias may be null)
// Tile: 64x64x16, 256 threads, 4x4 per-thread microtile.
// ---------------------------------------------------------------------------
template <bool BKM, bool SIG>
__global__ __launch_bounds__(256)
void gemm_k(const float* __restrict__ A, int lda, long long sA,
            const float* __restrict__ B, int ldb, long long sB,
            float* __restrict__ C, int ldc, long long sC,
            int M, int N, int K,
            const float* __restrict__ bias, float scale)
{
    __shared__ float As[16][64];   // As[k][m]
    __shared__ float Bs[16][64];   // Bs[k][n]

    const int bz = blockIdx.z;
    const float* Ab = A + (long long)bz * sA;
    const float* Bb = B + (long long)bz * sB;
    float*       Cb = C + (long long)bz * sC;

    const int m0 = blockIdx.y * 64;
    const int n0 = blockIdx.x * 64;
    const int tid = threadIdx.x;
    const int tx = tid & 15;        // 0..15 -> 4 output cols
    const int ty = tid >> 4;        // 0..15 -> 4 output rows

    // A-tile loader mapping: 64 rows x 16 k, each thread loads 4 consecutive k
    const int ar = tid >> 2;        // 0..63 row within tile
    const int ak = (tid & 3) * 4;   // 0,4,8,12 k-offset

    float acc[4][4] = {};

    for (int k0 = 0; k0 < K; k0 += 16) {
        // ---- load A tile (transposed into As[k][m]) ----
        {
            const int m = m0 + ar;
            const bool mok = (m < M);
            const float* ap = Ab + (long long)m * lda + k0 + ak;
            #pragma unroll
            for (int i = 0; i < 4; i++) {
                const int k = k0 + ak + i;
                As[ak + i][ar] = (mok && k < K) ? ap[i] : 0.f;
            }
        }
        // ---- load B tile into Bs[k][n] ----
        if (BKM) {
            const int n = n0 + ar;
            const bool nok = (n < N);
            const float* bp = Bb + (long long)n * ldb + k0 + ak;
            #pragma unroll
            for (int i = 0; i < 4; i++) {
                const int k = k0 + ak + i;
                Bs[ak + i][ar] = (nok && k < K) ? bp[i] : 0.f;
            }
        } else {
            const int kr = tid >> 4;          // 0..15
            const int nc = (tid & 15) * 4;    // 0..60
            const int k = k0 + kr;
            const bool kok = (k < K);
            const float* bp = Bb + (long long)k * ldb + n0 + nc;
            #pragma unroll
            for (int i = 0; i < 4; i++) {
                const int n = n0 + nc + i;
                Bs[kr][nc + i] = (kok && n < N) ? bp[i] : 0.f;
            }
        }
        __syncthreads();

        // ---- compute ----
        #pragma unroll
        for (int k = 0; k < 16; k++) {
            float a[4], b[4];
            *(float4*)a = *(const float4*)&As[k][ty * 4];
            *(float4*)b = *(const float4*)&Bs[k][tx * 4];
            #pragma unroll
            for (int i = 0; i < 4; i++)
                #pragma unroll
                for (int j = 0; j < 4; j++)
                    acc[i][j] = fmaf(a[i], b[j], acc[i][j]);
        }
        __syncthreads();
    }

    // ---- epilogue ----
    #pragma unroll
    for (int i = 0; i < 4; i++) {
        const int m = m0 + ty * 4 + i;
        if (m >= M) continue;
        #pragma unroll
        for (int j = 0; j < 4; j++) {
            const int n = n0 + tx * 4 + j;
            if (n >= N) continue;
            float v = acc[i][j];
            if (SIG) {
                v = 1.0f / (1.0f + __expf(-v * scale));
            } else if (bias) {
                v += bias[n];
            }
            Cb[(long long)m * ldc + n] = v;
        }
    }
}

// ---------------------------------------------------------------------------
// Host launch
// ---------------------------------------------------------------------------
static inline int ceil_div(int a, int b) { return (a + b - 1) / b; }

extern "C" void kernel_launch(void* const* d_in, const int* in_sizes, int n_in,
                              void* d_out, int out_size)
{
    const float* q  = (const float*)d_in[0];
    const float* k  = (const float*)d_in[1];
    const float* v  = (const float*)d_in[2];
    const float* Wq = (const float*)d_in[3];
    const float* bq = (const float*)d_in[4];
    const float* Wk = (const float*)d_in[5];
    const float* bk = (const float*)d_in[6];
    const float* Wv = (const float*)d_in[7];
    const float* bv = (const float*)d_in[8];
    const float* Wo = (const float*)d_in[9];
    const float* bo = (const float*)d_in[10];
    float* out = (float*)d_out;

    float *qp, *kp, *vp, *ctx, *scores;
    cudaGetSymbolAddress((void**)&qp,     g_qp);
    cudaGetSymbolAddress((void**)&kp,     g_kp);
    cudaGetSymbolAddress((void**)&vp,     g_vp);
    cudaGetSymbolAddress((void**)&ctx,    g_ctx);
    cudaGetSymbolAddress((void**)&scores, g_scores);

    const float scale = 1.0f / sqrtf((float)AMP);
    const dim3 blk(256);

    // 1) QKV projections: [16384,257] = x[16384,257] @ W[257,257]^T + b
    {
        dim3 grid(ceil_div(ATT, 64), ceil_div(BT, 64), 1);
        gemm_k<true, false><<<grid, blk>>>(q, AMP, 0, Wq, AMP, 0,
                                           qp, LDP, 0, BT, ATT, AMP, bq, 0.f);
        gemm_k<true, false><<<grid, blk>>>(k, AMP, 0, Wk, AMP, 0,
                                           kp, LDP, 0, BT, ATT, AMP, bk, 0.f);
        gemm_k<true, false><<<grid, blk>>>(v, AMP, 0, Wv, AMP, 0,
                                           vp, LDP, 0, BT, ATT, AMP, bv, 0.f);
    }

    // 2) scores[b] = sigmoid( (qp[b] @ kp[b]^T) * scale )   [2048, 2048] x 8
    {
        dim3 grid(ceil_div(SEQ, 64), ceil_div(SEQ, 64), NBATCH);
        gemm_k<true, true><<<grid, blk>>>(
            qp, LDP, (long long)SEQ * LDP,
            kp, LDP, (long long)SEQ * LDP,
            scores, SEQ, (long long)SEQ * SEQ,
            SEQ, SEQ, ATT, nullptr, scale);
    }

    // 3) ctx[b] = scores[b] @ vp[b]   [2048, 257] x 8   (B is [K,N], n-contig)
    {
        dim3 grid(ceil_div(ATT, 64), ceil_div(SEQ, 64), NBATCH);
        gemm_k<false, false><<<grid, blk>>>(
            scores, SEQ, (long long)SEQ * SEQ,
            vp, LDP, (long long)SEQ * LDP,
            ctx, LDP, (long long)SEQ * LDP,
            SEQ, ATT, SEQ, nullptr, 0.f);
    }

    // 4) out = ctx @ Wo^T + bo   [16384, 257]  (batches contiguous in ctx)
    {
        dim3 grid(ceil_div(AMP, 64), ceil_div(BT, 64), 1);
        gemm_k<true, false><<<grid, blk>>>(ctx, LDP, 0, Wo, ATT, 0,
                                           out, AMP, 0, BT, AMP, ATT, bo, 0.f);
    }
}

// round 5
// speedup vs baseline: 3.4171x; 3.4110x over previous
#include <cuda_runtime.h>
#include <cstdint>
#include <math.h>

#define DIM 257
#define SEQ 2048
#define NB  8
#define BT  (NB * SEQ)        // 16384
#define KP  288               // padded K for dim-257 reductions (9 chunks of 32)
#define NPA 384               // padded N for B-operand buffers (3 full 128-tiles)
#define KC  32                // k per pipeline chunk
#define TSTRIDE 36            // smem row stride in floats (bank-conflict-free)
#define TILE_F (128 * TSTRIDE)          // floats per smem tile (4608)
#define SMEM_BYTES (2 * 2 * TILE_F * 4) // 73728

// ---------------- static device scratch (all fp32, tf32-rounded) ----------------
__device__ __align__(16) float g_x[3][(size_t)BT * KP];     // padded q,k,v
__device__ __align__(16) float g_W[4][(size_t)NPA * KP];    // padded weights (K-major)
__device__ __align__(16) float g_b[4][NPA];                 // padded biases
__device__ __align__(16) float g_qp[(size_t)BT * KP];       // projected Q
__device__ __align__(16) float g_kp[(size_t)BT * KP];       // projected K
__device__ __align__(16) float g_vt[(size_t)NB * NPA * SEQ];// V projected, transposed [b][n][t]
__device__ __align__(16) float g_s[(size_t)NB * SEQ * SEQ]; // sigmoid scores
__device__ __align__(16) float g_ct[(size_t)BT * KP];       // context

// ---------------- helpers ----------------
__device__ __forceinline__ float tf32r(float x) {
    uint32_t u;
    asm("cvt.rna.tf32.f32 %0, %1;" : "=r"(u) : "f"(x));
    return __uint_as_float(u);
}
__device__ __forceinline__ uint32_t s2u(const void* p) {
    uint32_t a;
    asm("{ .reg .u64 t; cvta.to.shared.u64 t, %1; cvt.u32.u64 %0, t; }" : "=r"(a) : "l"(p));
    return a;
}
__device__ __forceinline__ void cp16(uint32_t dst, const void* src) {
    asm volatile("cp.async.cg.shared.global [%0], [%1], 16;" :: "r"(dst), "l"(src));
}
__device__ __forceinline__ void mma_tf32(float* d, const uint32_t* a, const uint32_t* b) {
    asm volatile(
        "mma.sync.aligned.m16n8k8.row.col.f32.tf32.tf32.f32 "
        "{%0,%1,%2,%3}, {%4,%5,%6,%7}, {%8,%9}, {%0,%1,%2,%3};"
        : "+f"(d[0]), "+f"(d[1]), "+f"(d[2]), "+f"(d[3])
        : "r"(a[0]), "r"(a[1]), "r"(a[2]), "r"(a[3]), "r"(b[0]), "r"(b[1]));
}

// ---------------- prep kernels (pad + tf32 round) ----------------
__global__ void prep_x(const float* __restrict__ q, const float* __restrict__ k,
                       const float* __restrict__ v) {
    int i = blockIdx.x * 256 + threadIdx.x;
    if (i >= BT * KP) return;
    int r = i / KP, c = i - r * KP;
    long long si = (long long)r * DIM + c;
    g_x[0][i] = (c < DIM) ? tf32r(q[si]) : 0.f;
    g_x[1][i] = (c < DIM) ? tf32r(k[si]) : 0.f;
    g_x[2][i] = (c < DIM) ? tf32r(v[si]) : 0.f;
}
__global__ void prep_w(const float* W0, const float* b0, const float* W1, const float* b1,
                       const float* W2, const float* b2, const float* W3, const float* b3) {
    int i = blockIdx.x * 256 + threadIdx.x;
    const float* Ws[4] = {W0, W1, W2, W3};
    const float* bs[4] = {b0, b1, b2, b3};
    const int per = NPA * KP;
    if (i < 4 * per) {
        int w = i / per, rem = i - w * per, r = rem / KP, c = rem - r * KP;
        g_W[w][(size_t)r * KP + c] = (r < DIM && c < DIM) ? tf32r(Ws[w][r * DIM + c]) : 0.f;
    }
    if (i < 4 * NPA) {
        int w = i / NPA, n = i - w * NPA;
        g_b[w][n] = (n < DIM) ? bs[w][n] : 0.f;
    }
}

// ---------------- tf32 tensor-core GEMM: D[m,n] = sum_k A[m,k]*B[n,k] ----------------
// MODE 0: (+bias if non-null) -> tf32 round -> C[m*ldc+n], n < nstore
// MODE 1: +bias -> tf32 round -> transposed store C[((b*NPA+n)*SEQ)+t]  (V^T)
// MODE 2: sigmoid(v*scale)    -> tf32 round -> C[m*ldc+n]
// MODE 3: +bias               -> fp32 exact -> C[m*ldc+n], n < nstore  (final out)
template <int MODE>
__global__ __launch_bounds__(256)
void gemm(const float* __restrict__ A, long long sA, int lda,
          const float* __restrict__ B, long long sB, int ldb,
          int kc, float* __restrict__ C, long long sC, int ldc,
          int nstore, const float* __restrict__ bias, float scale)
{
    extern __shared__ __align__(16) float sm[];
    const int tid = threadIdx.x, wid = tid >> 5, lane = tid & 31;
    const int g = lane >> 2, t = lane & 3;
    const int bz = blockIdx.z, m0 = blockIdx.y * 128, n0 = blockIdx.x * 128;
    const int wm = (wid >> 1) * 32, wn = (wid & 1) * 64;

    const float* Ab = A + bz * sA + (long long)m0 * lda;
    const float* Bb = B + bz * sB + (long long)n0 * ldb;
    const uint32_t sb = s2u(sm);

    auto load = [&](int ck, int buf) {
        const float* ag = Ab + ck * KC;
        const float* bg = Bb + ck * KC;
        uint32_t da = sb + (uint32_t)buf * (2 * TILE_F * 4);
        uint32_t db = da + TILE_F * 4;
        #pragma unroll
        for (int i = 0; i < 4; i++) {
            int e = tid + i * 256;               // 0..1023
            int r = e >> 3, c = e & 7;
            uint32_t off = (uint32_t)(r * (TSTRIDE * 4) + c * 16);
            cp16(da + off, ag + (long long)r * lda + c * 4);
            cp16(db + off, bg + (long long)r * ldb + c * 4);
        }
        asm volatile("cp.async.commit_group;" ::: "memory");
    };

    float acc[2][8][4] = {};
    load(0, 0);

    for (int ck = 0; ck < kc; ++ck) {
        const int buf = ck & 1;
        if (ck + 1 < kc) {
            load(ck + 1, buf ^ 1);
            asm volatile("cp.async.wait_group 1;" ::: "memory");
        } else {
            asm volatile("cp.async.wait_group 0;" ::: "memory");
        }
        __syncthreads();

        const float* As = sm + buf * (2 * TILE_F);
        const float* Bs = As + TILE_F;
        #pragma unroll
        for (int ks = 0; ks < 4; ks++) {
            const int k0 = ks * 8;
            uint32_t a[2][4], b[8][2];
            #pragma unroll
            for (int mf = 0; mf < 2; mf++) {
                const int mr = wm + mf * 16 + g;
                a[mf][0] = __float_as_uint(As[mr * TSTRIDE + k0 + t]);
                a[mf][1] = __float_as_uint(As[(mr + 8) * TSTRIDE + k0 + t]);
                a[mf][2] = __float_as_uint(As[mr * TSTRIDE + k0 + t + 4]);
                a[mf][3] = __float_as_uint(As[(mr + 8) * TSTRIDE + k0 + t + 4]);
            }
            #pragma unroll
            for (int nf = 0; nf < 8; nf++) {
                const int nr = wn + nf * 8 + g;
                b[nf][0] = __float_as_uint(Bs[nr * TSTRIDE + k0 + t]);
                b[nf][1] = __float_as_uint(Bs[nr * TSTRIDE + k0 + t + 4]);
            }
            #pragma unroll
            for (int mf = 0; mf < 2; mf++)
                #pragma unroll
                for (int nf = 0; nf < 8; nf++)
                    mma_tf32(acc[mf][nf], a[mf], b[nf]);
        }
        __syncthreads();
    }

    // ---- epilogue ----
    const int bi = (MODE == 1) ? (m0 / SEQ) : 0;
    const int tl0 = (MODE == 1) ? (m0 % SEQ) : 0;

    #pragma unroll
    for (int mf = 0; mf < 2; mf++) {
        #pragma unroll
        for (int half = 0; half < 2; half++) {
            const int mloc = wm + mf * 16 + g + half * 8;
            const int m = m0 + mloc;
            #pragma unroll
            for (int nf = 0; nf < 8; nf++) {
                const int n = n0 + wn + nf * 8 + 2 * t;
                if (n >= nstore) continue;
                float v0 = acc[mf][nf][half * 2 + 0];
                float v1 = acc[mf][nf][half * 2 + 1];
                if (MODE == 2) {
                    v0 = tf32r(1.0f / (1.0f + __expf(-v0 * scale)));
                    v1 = tf32r(1.0f / (1.0f + __expf(-v1 * scale)));
                } else if (MODE == 3) {
                    v0 += bias[n];
                    v1 += bias[n + 1 < NPA ? n + 1 : n];
                } else {
                    if (bias) { v0 += bias[n]; v1 += bias[n + 1 < NPA ? n + 1 : n]; }
                    v0 = tf32r(v0); v1 = tf32r(v1);
                }
                if (MODE == 1) {
                    const int tl = tl0 + wm + mf * 16 + g + half * 8;
                    float* dst = C + ((long long)(bi * NPA + n)) * SEQ + tl;
                    dst[0] = v0;
                    if (n + 1 < nstore) dst[SEQ] = v1;
                } else if (MODE == 3) {
                    float* dst = C + bz * sC + (long long)m * ldc + n;
                    dst[0] = v0;
                    if (n + 1 < nstore) dst[1] = v1;
                } else {
                    float* dst = C + bz * sC + (long long)m * ldc + n;
                    *(float2*)dst = make_float2(v0, v1);   // nstore even, ldc even
                }
            }
        }
    }
}

// ---------------- host ----------------
extern "C" void kernel_launch(void* const* d_in, const int* in_sizes, int n_in,
                              void* d_out, int out_size)
{
    const float* q  = (const float*)d_in[0];
    const float* k  = (const float*)d_in[1];
    const float* v  = (const float*)d_in[2];
    const float* Wq = (const float*)d_in[3];
    const float* bq = (const float*)d_in[4];
    const float* Wk = (const float*)d_in[5];
    const float* bk = (const float*)d_in[6];
    const float* Wv = (const float*)d_in[7];
    const float* bv = (const float*)d_in[8];
    const float* Wo = (const float*)d_in[9];
    const float* bo = (const float*)d_in[10];
    float* out = (float*)d_out;

    float *x, *W, *bb, *qp, *kp, *vt, *s, *ct;
    cudaGetSymbolAddress((void**)&x,  g_x);
    cudaGetSymbolAddress((void**)&W,  g_W);
    cudaGetSymbolAddress((void**)&bb, g_b);
    cudaGetSymbolAddress((void**)&qp, g_qp);
    cudaGetSymbolAddress((void**)&kp, g_kp);
    cudaGetSymbolAddress((void**)&vt, g_vt);
    cudaGetSymbolAddress((void**)&s,  g_s);
    cudaGetSymbolAddress((void**)&ct, g_ct);

    cudaFuncSetAttribute(gemm<0>, cudaFuncAttributeMaxDynamicSharedMemorySize, SMEM_BYTES);
    cudaFuncSetAttribute(gemm<1>, cudaFuncAttributeMaxDynamicSharedMemorySize, SMEM_BYTES);
    cudaFuncSetAttribute(gemm<2>, cudaFuncAttributeMaxDynamicSharedMemorySize, SMEM_BYTES);
    cudaFuncSetAttribute(gemm<3>, cudaFuncAttributeMaxDynamicSharedMemorySize, SMEM_BYTES);

    const float scale = 1.0f / sqrtf((float)DIM);
    const size_t xs = (size_t)BT * KP, ws = (size_t)NPA * KP;

    prep_x<<<(BT * KP + 255) / 256, 256>>>(q, k, v);
    prep_w<<<(4 * NPA * KP + 255) / 256, 256>>>(Wq, bq, Wk, bk, Wv, bv, Wo, bo);

    // 1) projections: [BT,288] x [384,288]^T
    dim3 gp(3, BT / 128, 1);
    gemm<0><<<gp, 256, SMEM_BYTES>>>(x + 0 * xs, 0, KP, W + 0 * ws, 0, KP, KP / KC,
                                     qp, 0, KP, KP, bb + 0 * NPA, 0.f);
    gemm<0><<<gp, 256, SMEM_BYTES>>>(x + 1 * xs, 0, KP, W + 1 * ws, 0, KP, KP / KC,
                                     kp, 0, KP, KP, bb + 1 * NPA, 0.f);
    gemm<1><<<gp, 256, SMEM_BYTES>>>(x + 2 * xs, 0, KP, W + 2 * ws, 0, KP, KP / KC,
                                     vt, 0, KP, NPA, bb + 2 * NPA, 0.f);

    // 2) scores = sigmoid(qp @ kp^T * scale), per batch [2048,2048]
    dim3 gs(SEQ / 128, SEQ / 128, NB);
    gemm<2><<<gs, 256, SMEM_BYTES>>>(qp, (long long)SEQ * KP, KP,
                                     kp, (long long)SEQ * KP, KP, KP / KC,
                                     s, (long long)SEQ * SEQ, SEQ, SEQ, nullptr, scale);

    // 3) ctx = scores @ V   (B = V^T [384, 2048] per batch, K = 2048)
    dim3 gc(3, SEQ / 128, NB);
    gemm<0><<<gc, 256, SMEM_BYTES>>>(s, (long long)SEQ * SEQ, SEQ,
                                     vt, (long long)NPA * SEQ, SEQ, SEQ / KC,
                                     ct, (long long)SEQ * KP, KP, KP, nullptr, 0.f);

    // 4) out = ctx @ Wo^T + bo  (fp32 exact store, [BT, 257])
    gemm<3><<<gp, 256, SMEM_BYTES>>>(ct, 0, KP, W + 3 * ws, 0, KP, KP / KC,
                                     out, 0, DIM, DIM, bb + 3 * NPA, 0.f);
}

// round 6
// speedup vs baseline: 3.6291x; 1.0620x over previous
#include <cuda_runtime.h>
#include <cstdint>
#include <math.h>

#define DIM 257
#define SEQ 2048
#define NB  8
#define BT  (NB * SEQ)        // 16384
#define KP  288               // padded K for dim-257 reductions (9 chunks of 32)
#define NPA 384               // padded N for B-operand buffers (3 full 128-tiles)
#define KC  32                // k per pipeline chunk
#define TSTRIDE 36            // smem row stride in floats (bank-conflict-free)
#define TILE_F (128 * TSTRIDE)          // floats per smem tile (4608)
#define SMEM_BYTES (2 * 2 * TILE_F * 4) // 73728

// ---------------- static device scratch (all fp32, tf32-rounded) ----------------
__device__ __align__(16) float g_x[3][(size_t)BT * KP];     // padded q,k,v
__device__ __align__(16) float g_W[4][(size_t)NPA * KP];    // padded weights (K-major)
__device__ __align__(16) float g_b[4][NPA];                 // padded biases
__device__ __align__(16) float g_qp[(size_t)BT * KP];       // projected Q
__device__ __align__(16) float g_kp[(size_t)BT * KP];       // projected K
__device__ __align__(16) float g_vt[(size_t)NB * NPA * SEQ];// V projected, transposed [b][n][t]
__device__ __align__(16) float g_s[(size_t)NB * SEQ * SEQ]; // sigmoid scores
__device__ __align__(16) float g_ct[(size_t)BT * KP];       // context

// ---------------- helpers ----------------
__device__ __forceinline__ float tf32r(float x) {
    uint32_t u;
    asm("cvt.rna.tf32.f32 %0, %1;" : "=r"(u) : "f"(x));
    return __uint_as_float(u);
}
__device__ __forceinline__ uint32_t s2u(const void* p) {
    uint32_t a;
    asm("{ .reg .u64 t; cvta.to.shared.u64 t, %1; cvt.u32.u64 %0, t; }" : "=r"(a) : "l"(p));
    return a;
}
__device__ __forceinline__ void cp16(uint32_t dst, const void* src) {
    asm volatile("cp.async.cg.shared.global [%0], [%1], 16;" :: "r"(dst), "l"(src));
}
__device__ __forceinline__ void mma_tf32(float* d, const uint32_t* a, const uint32_t* b) {
    asm volatile(
        "mma.sync.aligned.m16n8k8.row.col.f32.tf32.tf32.f32 "
        "{%0,%1,%2,%3}, {%4,%5,%6,%7}, {%8,%9}, {%0,%1,%2,%3};"
        : "+f"(d[0]), "+f"(d[1]), "+f"(d[2]), "+f"(d[3])
        : "r"(a[0]), "r"(a[1]), "r"(a[2]), "r"(a[3]), "r"(b[0]), "r"(b[1]));
}

// ---------------- prep kernels (pad + tf32 round) ----------------
__global__ void prep_x(const float* __restrict__ q, const float* __restrict__ k,
                       const float* __restrict__ v) {
    int i = blockIdx.x * 256 + threadIdx.x;
    if (i >= BT * KP) return;
    int r = i / KP, c = i - r * KP;
    long long si = (long long)r * DIM + c;
    g_x[0][i] = (c < DIM) ? tf32r(q[si]) : 0.f;
    g_x[1][i] = (c < DIM) ? tf32r(k[si]) : 0.f;
    g_x[2][i] = (c < DIM) ? tf32r(v[si]) : 0.f;
}
__global__ void prep_w(const float* W0, const float* b0, const float* W1, const float* b1,
                       const float* W2, const float* b2, const float* W3, const float* b3) {
    int i = blockIdx.x * 256 + threadIdx.x;
    const float* Ws[4] = {W0, W1, W2, W3};
    const float* bs[4] = {b0, b1, b2, b3};
    const int per = NPA * KP;
    if (i < 4 * per) {
        int w = i / per, rem = i - w * per, r = rem / KP, c = rem - r * KP;
        g_W[w][(size_t)r * KP + c] = (r < DIM && c < DIM) ? tf32r(Ws[w][r * DIM + c]) : 0.f;
    }
    if (i < 4 * NPA) {
        int w = i / NPA, n = i - w * NPA;
        g_b[w][n] = (n < DIM) ? bs[w][n] : 0.f;
    }
}

// ---------------- tf32 tensor-core GEMM: D[m,n] = sum_k A[m,k]*B[n,k] ----------------
// 128x128 CTA tile, 4 warps, 64x64 warp tile (2x2 warp grid).
// MODE 0: (+bias if non-null) -> tf32 round -> C[m*ldc+n], n < nstore
// MODE 1: +bias -> tf32 round -> transposed store C[((b*NPA+n)*SEQ)+t]  (V^T)
// MODE 2: sigmoid(v*scale)    -> tf32 round -> C[m*ldc+n]
// MODE 3: +bias               -> fp32 exact -> C[m*ldc+n], n < nstore  (final out)
template <int MODE>
__global__ __launch_bounds__(128)
void gemm(const float* __restrict__ A, long long sA, int lda,
          const float* __restrict__ B, long long sB, int ldb,
          int kc, float* __restrict__ C, long long sC, int ldc,
          int nstore, const float* __restrict__ bias, float scale)
{
    extern __shared__ __align__(16) float sm[];
    const int tid = threadIdx.x, wid = tid >> 5, lane = tid & 31;
    const int g = lane >> 2, t = lane & 3;
    const int bz = blockIdx.z, m0 = blockIdx.y * 128, n0 = blockIdx.x * 128;
    const int wm = (wid >> 1) * 64, wn = (wid & 1) * 64;

    const float* Ab = A + bz * sA + (long long)m0 * lda;
    const float* Bb = B + bz * sB + (long long)n0 * ldb;
    const uint32_t sb = s2u(sm);

    auto load = [&](int ck, int buf) {
        const float* ag = Ab + ck * KC;
        const float* bg = Bb + ck * KC;
        uint32_t da = sb + (uint32_t)buf * (2 * TILE_F * 4);
        uint32_t db = da + TILE_F * 4;
        #pragma unroll
        for (int i = 0; i < 8; i++) {
            int e = tid + i * 128;               // 0..1023
            int r = e >> 3, c = e & 7;
            uint32_t off = (uint32_t)(r * (TSTRIDE * 4) + c * 16);
            cp16(da + off, ag + (long long)r * lda + c * 4);
            cp16(db + off, bg + (long long)r * ldb + c * 4);
        }
        asm volatile("cp.async.commit_group;" ::: "memory");
    };

    float acc[4][8][4] = {};
    load(0, 0);

    for (int ck = 0; ck < kc; ++ck) {
        const int buf = ck & 1;
        if (ck + 1 < kc) {
            load(ck + 1, buf ^ 1);
            asm volatile("cp.async.wait_group 1;" ::: "memory");
        } else {
            asm volatile("cp.async.wait_group 0;" ::: "memory");
        }
        __syncthreads();

        const float* As = sm + buf * (2 * TILE_F);
        const float* Bs = As + TILE_F;
        #pragma unroll
        for (int ks = 0; ks < 4; ks++) {
            const int k0 = ks * 8;
            uint32_t a[4][4], b[8][2];
            #pragma unroll
            for (int mf = 0; mf < 4; mf++) {
                const int mr = wm + mf * 16 + g;
                a[mf][0] = __float_as_uint(As[mr * TSTRIDE + k0 + t]);
                a[mf][1] = __float_as_uint(As[(mr + 8) * TSTRIDE + k0 + t]);
                a[mf][2] = __float_as_uint(As[mr * TSTRIDE + k0 + t + 4]);
                a[mf][3] = __float_as_uint(As[(mr + 8) * TSTRIDE + k0 + t + 4]);
            }
            #pragma unroll
            for (int nf = 0; nf < 8; nf++) {
                const int nr = wn + nf * 8 + g;
                b[nf][0] = __float_as_uint(Bs[nr * TSTRIDE + k0 + t]);
                b[nf][1] = __float_as_uint(Bs[nr * TSTRIDE + k0 + t + 4]);
            }
            #pragma unroll
            for (int mf = 0; mf < 4; mf++)
                #pragma unroll
                for (int nf = 0; nf < 8; nf++)
                    mma_tf32(acc[mf][nf], a[mf], b[nf]);
        }
        __syncthreads();
    }

    // ---- epilogue ----
    const int bi = (MODE == 1) ? (m0 / SEQ) : 0;
    const int tl0 = (MODE == 1) ? (m0 % SEQ) : 0;

    #pragma unroll
    for (int mf = 0; mf < 4; mf++) {
        #pragma unroll
        for (int half = 0; half < 2; half++) {
            const int mloc = wm + mf * 16 + g + half * 8;
            const int m = m0 + mloc;
            #pragma unroll
            for (int nf = 0; nf < 8; nf++) {
                const int n = n0 + wn + nf * 8 + 2 * t;
                if (n >= nstore) continue;
                float v0 = acc[mf][nf][half * 2 + 0];
                float v1 = acc[mf][nf][half * 2 + 1];
                if (MODE == 2) {
                    v0 = tf32r(1.0f / (1.0f + __expf(-v0 * scale)));
                    v1 = tf32r(1.0f / (1.0f + __expf(-v1 * scale)));
                } else if (MODE == 3) {
                    v0 += bias[n];
                    v1 += bias[n + 1 < NPA ? n + 1 : n];
                } else {
                    if (bias) { v0 += bias[n]; v1 += bias[n + 1 < NPA ? n + 1 : n]; }
                    v0 = tf32r(v0); v1 = tf32r(v1);
                }
                if (MODE == 1) {
                    const int tl = tl0 + mloc;
                    float* dst = C + ((long long)(bi * NPA + n)) * SEQ + tl;
                    dst[0] = v0;
                    if (n + 1 < nstore) dst[SEQ] = v1;
                } else if (MODE == 3) {
                    float* dst = C + bz * sC + (long long)m * ldc + n;
                    dst[0] = v0;
                    if (n + 1 < nstore) dst[1] = v1;
                } else {
                    float* dst = C + bz * sC + (long long)m * ldc + n;
                    *(float2*)dst = make_float2(v0, v1);   // nstore even, ldc even
                }
            }
        }
    }
}

// ---------------- host ----------------
extern "C" void kernel_launch(void* const* d_in, const int* in_sizes, int n_in,
                              void* d_out, int out_size)
{
    const float* q  = (const float*)d_in[0];
    const float* k  = (const float*)d_in[1];
    const float* v  = (const float*)d_in[2];
    const float* Wq = (const float*)d_in[3];
    const float* bq = (const float*)d_in[4];
    const float* Wk = (const float*)d_in[5];
    const float* bk = (const float*)d_in[6];
    const float* Wv = (const float*)d_in[7];
    const float* bv = (const float*)d_in[8];
    const float* Wo = (const float*)d_in[9];
    const float* bo = (const float*)d_in[10];
    float* out = (float*)d_out;

    float *x, *W, *bb, *qp, *kp, *vt, *s, *ct;
    cudaGetSymbolAddress((void**)&x,  g_x);
    cudaGetSymbolAddress((void**)&W,  g_W);
    cudaGetSymbolAddress((void**)&bb, g_b);
    cudaGetSymbolAddress((void**)&qp, g_qp);
    cudaGetSymbolAddress((void**)&kp, g_kp);
    cudaGetSymbolAddress((void**)&vt, g_vt);
    cudaGetSymbolAddress((void**)&s,  g_s);
    cudaGetSymbolAddress((void**)&ct, g_ct);

    cudaFuncSetAttribute(gemm<0>, cudaFuncAttributeMaxDynamicSharedMemorySize, SMEM_BYTES);
    cudaFuncSetAttribute(gemm<1>, cudaFuncAttributeMaxDynamicSharedMemorySize, SMEM_BYTES);
    cudaFuncSetAttribute(gemm<2>, cudaFuncAttributeMaxDynamicSharedMemorySize, SMEM_BYTES);
    cudaFuncSetAttribute(gemm<3>, cudaFuncAttributeMaxDynamicSharedMemorySize, SMEM_BYTES);

    const float scale = 1.0f / sqrtf((float)DIM);
    const size_t xs = (size_t)BT * KP, ws = (size_t)NPA * KP;

    prep_x<<<(BT * KP + 255) / 256, 256>>>(q, k, v);
    prep_w<<<(4 * NPA * KP + 255) / 256, 256>>>(Wq, bq, Wk, bk, Wv, bv, Wo, bo);

    // 1) projections: [BT,288] x [384,288]^T
    dim3 gp(3, BT / 128, 1);
    gemm<0><<<gp, 128, SMEM_BYTES>>>(x + 0 * xs, 0, KP, W + 0 * ws, 0, KP, KP / KC,
                                     qp, 0, KP, KP, bb + 0 * NPA, 0.f);
    gemm<0><<<gp, 128, SMEM_BYTES>>>(x + 1 * xs, 0, KP, W + 1 * ws, 0, KP, KP / KC,
                                     kp, 0, KP, KP, bb + 1 * NPA, 0.f);
    gemm<1><<<gp, 128, SMEM_BYTES>>>(x + 2 * xs, 0, KP, W + 2 * ws, 0, KP, KP / KC,
                                     vt, 0, KP, NPA, bb + 2 * NPA, 0.f);

    // 2) scores = sigmoid(qp @ kp^T * scale), per batch [2048,2048]
    dim3 gs(SEQ / 128, SEQ / 128, NB);
    gemm<2><<<gs, 128, SMEM_BYTES>>>(qp, (long long)SEQ * KP, KP,
                                     kp, (long long)SEQ * KP, KP, KP / KC,
                                     s, (long long)SEQ * SEQ, SEQ, SEQ, nullptr, scale);

    // 3) ctx = scores @ V   (B = V^T [384, 2048] per batch, K = 2048)
    dim3 gc(3, SEQ / 128, NB);
    gemm<0><<<gc, 128, SMEM_BYTES>>>(s, (long long)SEQ * SEQ, SEQ,
                                     vt, (long long)NPA * SEQ, SEQ, SEQ / KC,
                                     ct, (long long)SEQ * KP, KP, KP, nullptr, 0.f);

    // 4) out = ctx @ Wo^T + bo  (fp32 exact store, [BT, 257])
    gemm<3><<<gp, 128, SMEM_BYTES>>>(ct, 0, KP, W + 3 * ws, 0, KP, KP / KC,
                                     out, 0, DIM, DIM, bb + 3 * NPA, 0.f);
}